// round 17
// baseline (speedup 1.0000x reference)
#include <cuda_runtime.h>
#include <cuda_bf16.h>
#include <math.h>
#include <stdint.h>

// Problem constants
#define NT    65536
#define DD    256
#define MM    512
#define NTD   16777216
#define MT    128                 // rows per score-CTA
#define NB    (NT / MT)           // 512 score CTAs
#define TAU   0.03f               // guard band ~8 sigma of bf16 hi-only error
#define GB    2048                // gather blocks (32 rows each)
#define RB    128                 // rescore blocks

// K1 smem byte offsets
#define SM_A     0                // A hi: 128 rows x 512B (256 bf16, full K)
#define SM_B0    65536            // B chunk buf0: 128 codes x 128B (64 bf16)
#define SM_B1    81920            // B chunk buf1
#define SM_CS    98304            // c_j [512] f32
#define SM_M1    100352           // [128] f32
#define SM_I1    100864           // [128] int
#define SM_M2    101376           // [128] f32
#define SM_I2    101888           // [128] int
#define SM_M3    102400           // [128] f32
#define SMEM_TOTAL 102944

// Device scratch
__device__ float         g_embn[MM * DD];   // normalized codebook [j][k] fp32
__device__ __nv_bfloat16 g_ebH[MM * DD];    // bf16 hi [j][k]
__device__ float         g_c[MM];
__device__ int           g_rid[NT];         // selected code per row
__device__ float         g_loss_part[GB];
__device__ int           g_hist[MM];
// rescore queues
__device__ int           g_nA, g_nB;
__device__ int           g_qArow[NT];
__device__ int           g_qBrow[NT];
__device__ int           g_qB1[NT];
__device__ int           g_qB2[NT];

__device__ __forceinline__ uint32_t smem_u32(const void* p) {
    uint32_t a;
    asm("{ .reg .u64 t; cvta.to.shared.u64 t, %1; cvt.u32.u64 %0, t; }" : "=r"(a) : "l"(p));
    return a;
}
__device__ __forceinline__ void ldsm4(uint32_t* r, uint32_t addr) {
    asm volatile("ldmatrix.sync.aligned.m8n8.x4.shared.b16 {%0,%1,%2,%3}, [%4];"
        : "=r"(r[0]), "=r"(r[1]), "=r"(r[2]), "=r"(r[3]) : "r"(addr));
}
__device__ __forceinline__ void mma_bf16(float* d, const uint32_t* a,
                                         uint32_t b0, uint32_t b1) {
    asm volatile("mma.sync.aligned.m16n8k16.row.col.f32.bf16.bf16.f32 "
        "{%0,%1,%2,%3}, {%4,%5,%6,%7}, {%8,%9}, {%0,%1,%2,%3};"
        : "+f"(d[0]), "+f"(d[1]), "+f"(d[2]), "+f"(d[3])
        : "r"(a[0]), "r"(a[1]), "r"(a[2]), "r"(a[3]), "r"(b0), "r"(b1));
}
#define CP_ASYNC16(saddr, gptr) \
    asm volatile("cp.async.cg.shared.global [%0], [%1], 16;" :: "r"(saddr), "l"(gptr))
#define CP_COMMIT() asm volatile("cp.async.commit_group;" ::: "memory")
#define CP_WAIT0()  asm volatile("cp.async.wait_group 0;" ::: "memory")

// packed f32x2 (per-lane IEEE RN)
#define ADD2(d, a, b) asm("add.rn.f32x2 %0, %1, %2;" : "=l"(d) : "l"(a), "l"(b))
#define MUL2(d, a, b) asm("mul.rn.f32x2 %0, %1, %2;" : "=l"(d) : "l"(a), "l"(b))
#define FMA2(d, a, b) asm("fma.rn.f32x2 %0, %1, %2, %0;" : "+l"(d) : "l"(a), "l"(b))
#define UNPK2(lo, hi, v) asm("mov.b64 {%0,%1}, %2;" : "=f"(lo), "=f"(hi) : "l"(v))
#define SGN2 0x8000000080000000ull
#define HALF2C 0x3F0000003F000000ull

union F4U { float4 f; unsigned long long u[2]; };

// top-3 tracker (indices for top-2 only; m3 is a value bound)
struct Top3 { float m1, m2, m3; int i1, i2; };
__device__ __forceinline__ void t3_ins(Top3& t, float m, int i) {
    if (m < t.m1 || (m == t.m1 && i < t.i1)) {
        t.m3 = t.m2; t.m2 = t.m1; t.i2 = t.i1; t.m1 = m; t.i1 = i;
    } else if (m < t.m2 || (m == t.m2 && i < t.i2)) {
        t.m3 = t.m2; t.m2 = m; t.i2 = i;
    } else if (m < t.m3) t.m3 = m;
}

// exact XLA-order sx for one row: full warp, lane l takes float4 l and 32+l
__device__ __forceinline__ float warp_sx(const float4* xr4, int lid) {
    float4 a  = xr4[lid];
    float4 bq = xr4[32 + lid];
    float s = 0.0f;
    s = __fadd_rn(s, __fmul_rn(a.x, a.x));
    s = __fadd_rn(s, __fmul_rn(a.y, a.y));
    s = __fadd_rn(s, __fmul_rn(a.z, a.z));
    s = __fadd_rn(s, __fmul_rn(a.w, a.w));
    s = __fadd_rn(s, __fmul_rn(bq.x, bq.x));
    s = __fadd_rn(s, __fmul_rn(bq.y, bq.y));
    s = __fadd_rn(s, __fmul_rn(bq.z, bq.z));
    s = __fadd_rn(s, __fmul_rn(bq.w, bq.w));
#pragma unroll
    for (int off = 16; off > 0; off >>= 1)
        s = __fadd_rn(s, __shfl_xor_sync(0xffffffffu, s, off));
    return s;
}

// exact dot chain, bit-identical to R6 (sequential ascending-k fmaf)
__device__ __forceinline__ float exact_metric(const float4* xr4, int code,
                                              float c, float sx) {
    const float4* er4 = (const float4*)(g_embn + code * DD);
    float acc = 0.0f;
#pragma unroll 8
    for (int q = 0; q < 64; q++) {
        float4 a = xr4[q], e = er4[q];
        acc = fmaf(a.x, e.x, acc);
        acc = fmaf(a.y, e.y, acc);
        acc = fmaf(a.z, e.z, acc);
        acc = fmaf(a.w, e.w, acc);
    }
    return __fadd_rn(__fadd_rn(c, sx), -2.0f * acc);
}

// ---------------------------------------------------------------------------
// Prep: normalize codebook, bf16 hi split, c_j, zero hist + queue counters
// ---------------------------------------------------------------------------
__global__ void vq_prep_kernel(const float* __restrict__ emb) {
    int j = blockIdx.x;
    int t = threadIdx.x;
    __shared__ float sq[256];
    __shared__ float norm_s;

    if (j == 0 && t == 0) { g_nA = 0; g_nB = 0; }

    float v = emb[j * DD + t];
    sq[t] = __fmul_rn(v, v);
    __syncthreads();
    if (t < 32) {
        float s = 0.0f;
#pragma unroll
        for (int c = 0; c < 4; c++) s = __fadd_rn(s, sq[4 * t + c]);
#pragma unroll
        for (int c = 0; c < 4; c++) s = __fadd_rn(s, sq[128 + 4 * t + c]);
#pragma unroll
        for (int off = 16; off > 0; off >>= 1)
            s = __fadd_rn(s, __shfl_xor_sync(0xffffffffu, s, off));
        if (t == 0) norm_s = sqrtf(s);
    }
    __syncthreads();

    float e = v / __fadd_rn(norm_s, 1e-4f);
    g_embn[j * DD + t] = e;
    g_ebH[j * DD + t] = __float2bfloat16(e);

    sq[t] = __fmul_rn(e, e);
    __syncthreads();
    if (t < 32) {
        float s = 0.0f;
#pragma unroll
        for (int c = 0; c < 4; c++) s = __fadd_rn(s, sq[4 * t + c]);
#pragma unroll
        for (int c = 0; c < 4; c++) s = __fadd_rn(s, sq[128 + 4 * t + c]);
#pragma unroll
        for (int off = 16; off > 0; off >>= 1)
            s = __fadd_rn(s, __shfl_xor_sync(0xffffffffu, s, off));
        if (t == 0) { g_c[j] = s; g_hist[j] = 0; }
    }
}

// ---------------------------------------------------------------------------
// K1: mma scores + top-3 + classify. NO exact math here (register purity).
// 512 CTAs x 256 thr.
// ---------------------------------------------------------------------------
__global__ void __launch_bounds__(256, 2)
vq_score_kernel(const float* __restrict__ x) {
    extern __shared__ char smem[];
    const uint32_t sb = smem_u32(smem);
    const int tid = threadIdx.x;
    const int wid = tid >> 5;
    const int lid = tid & 31;
    const long r0 = (long)blockIdx.x * MT;

    float* c_s   = (float*)(smem + SM_CS);
    float* m1_s  = (float*)(smem + SM_M1);
    int*   i1_s  = (int*)(smem + SM_I1);
    float* m2_s  = (float*)(smem + SM_M2);
    int*   i2_s  = (int*)(smem + SM_I2);
    float* m3_s  = (float*)(smem + SM_M3);

    const float4* xg4 = (const float4*)(x + r0 * DD);   // 64 float4 per row

    // c_j
    for (int i = tid; i < MM; i += 256) c_s[i] = g_c[i];

    // A fill (once): x -> bf16 hi (packed cvt), swizzled [row][256 bf16] pitch 512B
#pragma unroll
    for (int i = 0; i < 32; i++) {
        int v   = tid + i * 256;      // 8192 float4
        int row = v >> 6;
        int kq  = v & 63;
        float4 f = xg4[row * 64 + kq];
        __nv_bfloat162 b01 = __floats2bfloat162_rn(f.x, f.y);
        __nv_bfloat162 b23 = __floats2bfloat162_rn(f.z, f.w);
        uint2 st;
        st.x = *(uint32_t*)&b01;
        st.y = *(uint32_t*)&b23;
        uint32_t ofs = (uint32_t)(kq * 8) ^ ((uint32_t)(row & 7) * 16);
        *(uint2*)(smem + SM_A + row * 512 + ofs) = st;
    }

    // prefetch chunk 0 into buf0
    {
#pragma unroll
        for (int i = 0; i < 4; i++) {
            int v = tid + i * 256;
            int j = v >> 3, q = v & 7;
            const char* src = (const char*)g_ebH + ((long)j * DD + q * 8) * 2;
            uint32_t dst = sb + SM_B0 + j * 128 +
                           (((uint32_t)(q * 16)) ^ ((uint32_t)(j & 7) * 16));
            CP_ASYNC16(dst, src);
        }
        CP_COMMIT();
    }

    // lane-invariant ldmatrix address pieces (proven R13-R16)
    const int arow = wid * 16 + (lid & 7) + (lid & 8);
    const uint32_t a_rowoff = (uint32_t)arow * 512;
    const uint32_t a_rowxor = (uint32_t)(arow & 7) * 16;
    const uint32_t a_coladd = (uint32_t)(lid & 16);
    const int      b_lrow   = (lid & 7) + ((lid & 16) >> 1);
    const uint32_t b_coladd = (uint32_t)(lid & 8) * 2;

    const int r_lo = wid * 16 + (lid >> 2);
    const int r_hi = r_lo + 8;

    Top3 t3[2];
#pragma unroll
    for (int s = 0; s < 2; s++) {
        t3[s].m1 = t3[s].m2 = t3[s].m3 = INFINITY;
        t3[s].i1 = t3[s].i2 = 0;
    }

    int cc = 0;
    for (int ct = 0; ct < 4; ct++) {
        float acc[16][4];
#pragma unroll
        for (int n = 0; n < 16; n++)
#pragma unroll
            for (int c = 0; c < 4; c++) acc[n][c] = 0.0f;

        for (int kc = 0; kc < 4; kc++) {
            // single barrier per chunk: all warps finished chunk cc-1's mma,
            // so prefetching cc+1 into buf (cc-1)&1 is safe.
            CP_WAIT0();
            __syncthreads();

            if (cc < 15) {
                int nct = (cc + 1) >> 2, nkc = (cc + 1) & 3;
                uint32_t nb = sb + (((cc + 1) & 1) ? SM_B1 : SM_B0);
#pragma unroll
                for (int i = 0; i < 4; i++) {
                    int v = tid + i * 256;
                    int j = v >> 3, q = v & 7;
                    const char* src = (const char*)g_ebH +
                        ((long)(nct * 128 + j) * DD + nkc * 64 + q * 8) * 2;
                    uint32_t dst = nb + j * 128 +
                        (((uint32_t)(q * 16)) ^ ((uint32_t)(j & 7) * 16));
                    CP_ASYNC16(dst, src);
                }
                CP_COMMIT();
            }

            const uint32_t bbase = sb + ((cc & 1) ? SM_B1 : SM_B0);
#pragma unroll
            for (int ks = 0; ks < 4; ks++) {
                uint32_t cbA = (uint32_t)(kc * 128 + ks * 32) + a_coladd;
                uint32_t ah[4];
                ldsm4(ah, sb + SM_A + a_rowoff + (cbA ^ a_rowxor));
                uint32_t cbB = (uint32_t)(ks * 32) + b_coladd;
#pragma unroll
                for (int nt2 = 0; nt2 < 8; nt2++) {
                    int code = nt2 * 16 + b_lrow;
                    uint32_t boff = (uint32_t)code * 128 +
                                    (cbB ^ ((uint32_t)(code & 7) * 16));
                    uint32_t bh[4];
                    ldsm4(bh, bbase + boff);
                    mma_bf16(acc[nt2 * 2],     ah, bh[0], bh[1]);
                    mma_bf16(acc[nt2 * 2 + 1], ah, bh[2], bh[3]);
                }
            }
            cc++;
        }

        // fold this code tile into top-3 (sx cancels within-row; omitted)
#pragma unroll
        for (int nt = 0; nt < 16; nt++) {
            int j0 = ct * 128 + nt * 8 + (lid & 3) * 2;
#pragma unroll
            for (int c = 0; c < 4; c++) {
                int slot = c >> 1;
                int j = j0 + (c & 1);
                float m = fmaf(-2.0f, acc[nt][c], c_s[j]);
                t3_ins(t3[slot], m, j);
            }
        }
    }

    // merge across the 4 lanes sharing each row (xor 1, 2)
#pragma unroll
    for (int s = 0; s < 2; s++) {
#pragma unroll
        for (int off = 1; off <= 2; off <<= 1) {
            float om1 = __shfl_xor_sync(0xffffffffu, t3[s].m1, off);
            int   oi1 = __shfl_xor_sync(0xffffffffu, t3[s].i1, off);
            float om2 = __shfl_xor_sync(0xffffffffu, t3[s].m2, off);
            int   oi2 = __shfl_xor_sync(0xffffffffu, t3[s].i2, off);
            float om3 = __shfl_xor_sync(0xffffffffu, t3[s].m3, off);
            t3_ins(t3[s], om1, oi1);
            t3_ins(t3[s], om2, oi2);
            if (om3 < t3[s].m3) t3[s].m3 = om3;
        }
    }
    __syncthreads();
    if ((lid & 3) == 0) {
        m1_s[r_lo] = t3[0].m1; i1_s[r_lo] = t3[0].i1;
        m2_s[r_lo] = t3[0].m2; i2_s[r_lo] = t3[0].i2; m3_s[r_lo] = t3[0].m3;
        m1_s[r_hi] = t3[1].m1; i1_s[r_hi] = t3[1].i1;
        m2_s[r_hi] = t3[1].m2; i2_s[r_hi] = t3[1].i2; m3_s[r_hi] = t3[1].m3;
    }
    __syncthreads();

    // classify rows -> g_rid + global queues (no exact math in this kernel)
    if (tid < MT) {
        int rowg = (int)(r0 + tid);
        g_rid[rowg] = i1_s[tid];
        float lim = m1_s[tid] + TAU;
        if (m3_s[tid] <= lim) {                 // rare: full exact rescan
            int p = atomicAdd(&g_nA, 1);
            g_qArow[p] = rowg;
        } else if (m2_s[tid] <= lim) {          // pair rescore
            int p = atomicAdd(&g_nB, 1);
            g_qBrow[p] = rowg;
            g_qB1[p] = i1_s[tid];
            g_qB2[p] = i2_s[tid];
        }
    }
}

// ---------------------------------------------------------------------------
// K1.5: exact rescore of queued rows. 128 blocks x 256 thr.
// Pairs: one warp per row. Fulls: one block per row (512 codes / 256 thr).
// All exact chains / orders / tie-breaks identical to the passing kernels.
// ---------------------------------------------------------------------------
__global__ void __launch_bounds__(256)
vq_rescore_kernel(const float* __restrict__ x) {
    __shared__ float sx_sh;
    __shared__ float rv[8];
    __shared__ int   ri[8];
    const int tid = threadIdx.x;
    const int wid = tid >> 5;
    const int lid = tid & 31;

    // pairs: warp-parallel over queue B
    int nB = g_nB;
    for (int e = blockIdx.x * 8 + wid; e < nB; e += RB * 8) {
        int row = g_qBrow[e];
        const float4* xr4 = (const float4*)(x + (long)row * DD);
        float sx = warp_sx(xr4, lid);
        int code = 0;
        float me = INFINITY;
        if (lid < 2) {
            code = (lid & 1) ? g_qB2[e] : g_qB1[e];
            me = exact_metric(xr4, code, g_c[code], sx);
        }
        float om = __shfl_xor_sync(0xffffffffu, me, 1);
        int   oc = __shfl_xor_sync(0xffffffffu, code, 1);
        if (lid == 0)
            g_rid[row] = (me < om || (me == om && code < oc)) ? code : oc;
    }

    // fulls: block-cooperative over queue A
    int nA = g_nA;
    for (int f = blockIdx.x; f < nA; f += RB) {
        __syncthreads();
        int row = g_qArow[f];
        const float4* xr4 = (const float4*)(x + (long)row * DD);
        if (wid == 0) {
            float s = warp_sx(xr4, lid);
            if (lid == 0) sx_sh = s;
        }
        __syncthreads();
        float sx = sx_sh;

        // two interleaved exact chains per thread (each chain is the exact
        // sequential ascending-k fmaf order; interleaving preserves both)
        int c1 = tid, c2 = tid + 256;
        const float4* e1 = (const float4*)(g_embn + c1 * DD);
        const float4* e2 = (const float4*)(g_embn + c2 * DD);
        float a1 = 0.0f, a2 = 0.0f;
#pragma unroll 4
        for (int q = 0; q < 64; q++) {
            float4 xv = xr4[q];
            float4 u = e1[q];
            a1 = fmaf(xv.x, u.x, a1);
            a1 = fmaf(xv.y, u.y, a1);
            a1 = fmaf(xv.z, u.z, a1);
            a1 = fmaf(xv.w, u.w, a1);
            float4 w = e2[q];
            a2 = fmaf(xv.x, w.x, a2);
            a2 = fmaf(xv.y, w.y, a2);
            a2 = fmaf(xv.z, w.z, a2);
            a2 = fmaf(xv.w, w.w, a2);
        }
        float me1 = __fadd_rn(__fadd_rn(g_c[c1], sx), -2.0f * a1);
        float me2 = __fadd_rn(__fadd_rn(g_c[c2], sx), -2.0f * a2);
        // c1 < c2 always, so <= keeps the lower index on ties
        float bv = (me1 <= me2) ? me1 : me2;
        int   bi = (me1 <= me2) ? c1  : c2;
        // warp argmin (lowest index ties)
#pragma unroll
        for (int off = 16; off > 0; off >>= 1) {
            float ov = __shfl_xor_sync(0xffffffffu, bv, off);
            int   oi = __shfl_xor_sync(0xffffffffu, bi, off);
            if (ov < bv || (ov == bv && oi < bi)) { bv = ov; bi = oi; }
        }
        if (lid == 0) { rv[wid] = bv; ri[wid] = bi; }
        __syncthreads();
        if (tid == 0) {
            float best = rv[0]; int idx = ri[0];
            for (int w = 1; w < 8; w++) {
                if (rv[w] < best || (rv[w] == best && ri[w] < idx)) {
                    best = rv[w]; idx = ri[w];
                }
            }
            g_rid[row] = idx;
        }
    }
}

// ---------------------------------------------------------------------------
// K2: gather + straight-through + loss + histogram. 2048 blocks x 256 thr.
// Output arithmetic bit-identical to R15/R16 packed-f32x2 epilogue.
// ---------------------------------------------------------------------------
__global__ void __launch_bounds__(256)
vq_gather_kernel(const float* __restrict__ x,
                 const float* __restrict__ emb,
                 float* __restrict__ out) {
    __shared__ float lred[8];
    const int tid = threadIdx.x;
    const int wid = tid >> 5;
    const int lid = tid & 31;
    const long row = (long)blockIdx.x * 32 + (tid >> 3);
    const int  kb  = (tid & 7) * 32;          // floats

    int idx = g_rid[row];
    if ((tid & 7) == 0) atomicAdd(&g_hist[idx], 1);
    const float4* eq = (const float4*)(emb + (long)idx * DD + kb);
    const float4* xq = (const float4*)(x + row * DD + kb);
    float4*       og = (float4*)(out + row * DD + kb);

    unsigned long long lacc = 0ull;
#pragma unroll
    for (int i = 0; i < 8; i++) {
        F4U Q, X, O;
        Q.f = eq[i];
        X.f = xq[i];
#pragma unroll
        for (int h = 0; h < 2; h++) {
            unsigned long long nx = X.u[h] ^ SGN2;
            unsigned long long t1, t2, t3v;
            ADD2(t1, Q.u[h], nx);        // q - x
            ADD2(t2, X.u[h], t1);        // x + (q - x)
            ADD2(t3v, t2, Q.u[h]);       // + q
            MUL2(O.u[h], t3v, (unsigned long long)HALF2C);  // * 0.5
            unsigned long long nq = Q.u[h] ^ SGN2;
            unsigned long long d;
            ADD2(d, X.u[h], nq);         // x - q
            FMA2(lacc, d, d);
        }
        og[i] = O.f;
    }
    float llo, lhi;
    UNPK2(llo, lhi, lacc);
    float lsum = llo + lhi;
#pragma unroll
    for (int off = 16; off > 0; off >>= 1)
        lsum += __shfl_down_sync(0xffffffffu, lsum, off);
    if (lid == 0) lred[wid] = lsum;
    __syncthreads();
    if (tid == 0) {
        float tot = 0.0f;
        for (int w = 0; w < 8; w++) tot += lred[w];
        g_loss_part[blockIdx.x] = tot;
    }
}

// ---------------------------------------------------------------------------
// Finalize: loss mean + perplexity. 1 block x 512 threads.
// ---------------------------------------------------------------------------
__global__ void vq_finalize_kernel(float* __restrict__ out, int write_scalars) {
    __shared__ float red[512];
    int t = threadIdx.x;

    float s = 0.0f;
#pragma unroll
    for (int q = 0; q < 4; q++) s += g_loss_part[t + q * 512];
    red[t] = s;
    __syncthreads();
#pragma unroll
    for (int st = 256; st > 0; st >>= 1) {
        if (t < st) red[t] += red[t + st];
        __syncthreads();
    }
    float loss = red[0] / (float)NTD;

    float p = (float)g_hist[t] * (1.0f / (float)NT);
    red[t] = p * logf(p + 1e-10f);
    __syncthreads();
#pragma unroll
    for (int st = 256; st > 0; st >>= 1) {
        if (t < st) red[t] += red[t + st];
        __syncthreads();
    }
    if (t == 0 && write_scalars) {
        out[NTD]     = loss;
        out[NTD + 1] = expf(-red[0]);
    }
}

// ---------------------------------------------------------------------------
extern "C" void kernel_launch(void* const* d_in, const int* in_sizes, int n_in,
                              void* d_out, int out_size) {
    const float* x   = (const float*)d_in[0];
    const float* emb = (const float*)d_in[1];
    float* out = (float*)d_out;

    cudaFuncSetAttribute(vq_score_kernel,
                         cudaFuncAttributeMaxDynamicSharedMemorySize, SMEM_TOTAL);

    vq_prep_kernel<<<MM, 256>>>(emb);
    vq_score_kernel<<<NB, 256, SMEM_TOTAL>>>(x);
    vq_rescore_kernel<<<RB, 256>>>(x);
    vq_gather_kernel<<<GB, 256>>>(x, emb, out);
    int write_scalars = (out_size >= NTD + 2) ? 1 : 0;
    vq_finalize_kernel<<<1, 512>>>(out, write_scalars);
}